// round 8
// baseline (speedup 1.0000x reference)
#include <cuda_runtime.h>
#include <math.h>

// Problem constants
#define MM       2048           // patches
#define NC       4              // compartments
#define NSTEPS   128
#define BETA_F   0.25f
#define TRAJ_ELEMS (NSTEPS * MM * (NC + 1))   // 1310720

// 128 persistent blocks, 16 rows of R each, 256 threads.
// SMEM ~136KB => 1 block/SM => all 128 blocks co-resident (148/152 SMs),
// so the software grid barrier cannot deadlock.
#define NBLK     128
#define ROWS     16
#define NTHREADS 256
#define NGRP     16             // barrier tree: 16 groups x 8 blocks
#define NCOPY    8              // broadcast flag copies
#define PAD      32             // 32 uints = 128B: one word per L2 line

// SMEM: R tile (16*2048 f32) + x vector (2048 f32) + 32 partials + 16 doubles
#define SMEM_BYTES ((ROWS * MM + MM + 32) * 4 + 16 * 8)

// -------- persistent device state (monotonic / re-derived every launch) -----
__device__ float        g_x[MM];              // rho[:,0] (phase-A input)
__device__ float        g_p[MM];              // infect_prob (phase-B input)
__device__ float        g_part[NBLK * MM];    // per-block column partials
__device__ double       g_bsum[NBLK];         // per-block |traj| sums
__device__ unsigned int g_grp [NGRP * PAD];   // group arrival counters
__device__ unsigned int g_root[PAD];          // root arrival counter
__device__ unsigned int g_flag[NCOPY * PAD];  // broadcast generation copies

// Hybrid grid barrier (lessons R3/R4/R5/R7):
//  - ARRIVAL: 2-level atomic tree. <=8 RMW contenders per group counter,
//    <=16 at root => no 128-way same-address serialization (R3's tail cost).
//  - BROADCAST: root-last release-stores generation into 8 padded copies.
//  - WAIT: ONE poller per block (thread 0) on its copy (16 pollers/line),
//    throttled by __nanosleep => no L2 spin saturation (R4/R7's collapse).
// Monotonic counters: after gen n, grp[i]==8n, root==16n, flag[*]==n =>
// safe across CUDA-graph replays. acq_rel atomics + release store give
// transitive happens-before from every block's pre-barrier stores.
__device__ __forceinline__ void gridsync(unsigned int target) {
    __syncthreads();
    if (threadIdx.x == 0) {
        unsigned int v;
        asm volatile("atom.acq_rel.gpu.global.add.u32 %0, [%1], %2;"
                     : "=r"(v)
                     : "l"(&g_grp[(blockIdx.x >> 3) * PAD]), "r"(1u) : "memory");
        if (v == target * 8u - 1u) {                    // last of my 8-block group
            unsigned int r;
            asm volatile("atom.acq_rel.gpu.global.add.u32 %0, [%1], %2;"
                         : "=r"(r) : "l"(&g_root[0]), "r"(1u) : "memory");
            if (r == target * (unsigned)NGRP - 1u) {    // last block overall
                #pragma unroll
                for (int i = 0; i < NCOPY; i++)
                    asm volatile("st.release.gpu.u32 [%0], %1;"
                                 :: "l"(&g_flag[i * PAD]), "r"(target) : "memory");
            }
        }
        const unsigned int* myflag = &g_flag[(blockIdx.x & (NCOPY - 1)) * PAD];
        for (;;) {
            unsigned int f;
            asm volatile("ld.acquire.gpu.u32 %0, [%1];"
                         : "=r"(f) : "l"(myflag) : "memory");
            if ((int)(f - target) >= 0) break;
            __nanosleep(64);
        }
    }
    __syncthreads();
}

__global__ void __launch_bounds__(NTHREADS, 1)
metasim_kernel(const float* __restrict__ Rg,
               const float* __restrict__ Tg,
               const float* __restrict__ rho0,
               float* __restrict__ out,
               int out_size)
{
    extern __shared__ float smem[];
    float*  Rs   = smem;                   // [ROWS][MM]
    float*  xs   = Rs + ROWS * MM;         // [MM] staged vector
    float*  part = xs + MM;                // [16 rows][2 halves]
    double* dsum = (double*)(part + 32);   // [16], 8B aligned

    const int tid     = threadIdx.x;
    const int blk     = blockIdx.x;
    const int w       = tid >> 5;
    const int lane    = tid & 31;
    const int rowbase = blk * ROWS;
    const int rgrp    = w >> 1;            // 4-row group 0..3
    const int colhalf = w & 1;             // 0: cols 0..1023, 1: 1024..2047
    const int row0    = 4 * rgrp;

    // starting generation (all flag copies equal at every launch boundary)
    unsigned int gen = *((volatile unsigned int*)&g_flag[0]);

    // ---- load this block's 16 rows of R into SMEM (once) ----
    {
        const float4* Rg4 = (const float4*)Rg + (size_t)rowbase * (MM / 4);
        float4* Rs4 = (float4*)Rs;
        #pragma unroll 4
        for (int k = tid; k < ROWS * MM / 4; k += NTHREADS) Rs4[k] = Rg4[k];
    }

    // ---- per-row state lives in tid<16 ----
    const int myrow = rowbase + tid;       // valid for tid < ROWS
    float r0 = 0.f, r1 = 0.f, r2 = 0.f, r3 = 0.f, kk = 0.f;
    float Tr[16];
    if (tid < ROWS) {
        #pragma unroll
        for (int i = 0; i < 16; i++) Tr[i] = Tg[i];
        r0 = rho0[myrow * 4 + 0];
        r1 = rho0[myrow * 4 + 1];
        r2 = rho0[myrow * 4 + 2];
        r3 = rho0[myrow * 4 + 3];
        __stcg(&g_x[myrow], r0);           // initial x = rho0[:,0]
    }
    __syncthreads();                       // Rs ready for column sums

    // ---- deterministic ntot: per-block column partials (no float atomics) --
    for (int c = tid; c < MM; c += NTHREADS) {
        float s = 0.f;
        #pragma unroll
        for (int r = 0; r < ROWS; r++) s += Rs[r * MM + c];
        __stcg(&g_part[blk * MM + c], s);
    }
    gen++; gridsync(gen);                  // partials + g_x visible grid-wide

    if (tid < ROWS) {                      // ntot for own rows, fixed sum order
        float s = 0.f;
        #pragma unroll 8
        for (int bb = 0; bb < NBLK; bb++) s += __ldcg(&g_part[bb * MM + myrow]);
        kk = -BETA_F / s;
    }

    // warp's 4 R-row pointers over its column half (float4 granularity)
    const float4* Ra = (const float4*)(Rs + (row0 + 0) * MM) + colhalf * 256 + lane;
    const float4* Rb = (const float4*)(Rs + (row0 + 1) * MM) + colhalf * 256 + lane;
    const float4* Rc = (const float4*)(Rs + (row0 + 2) * MM) + colhalf * 256 + lane;
    const float4* Rd = (const float4*)(Rs + (row0 + 3) * MM) + colhalf * 256 + lane;
    float4* xs4  = (float4*)xs;
    const float4* xw = xs4 + colhalf * 256 + lane;

    double dAcc = 0.0;

    for (int t = 0; t < NSTEPS; t++) {
        // ===== Phase A: frac = R @ x ; p = 1 - exp(-beta*frac/ntot) =====
        {
            const float4* gx4 = (const float4*)g_x;
            xs4[tid]       = __ldcg(gx4 + tid);
            xs4[tid + 256] = __ldcg(gx4 + tid + 256);
        }
        __syncthreads();
        {
            float a0 = 0.f, a1 = 0.f, a2 = 0.f, a3 = 0.f;
            #pragma unroll 4
            for (int j = 0; j < 8; j++) {
                const float4 xv = xw[j * 32];
                const float4 u0 = Ra[j * 32];
                const float4 u1 = Rb[j * 32];
                const float4 u2 = Rc[j * 32];
                const float4 u3 = Rd[j * 32];
                a0 += u0.x*xv.x + u0.y*xv.y + u0.z*xv.z + u0.w*xv.w;
                a1 += u1.x*xv.x + u1.y*xv.y + u1.z*xv.z + u1.w*xv.w;
                a2 += u2.x*xv.x + u2.y*xv.y + u2.z*xv.z + u2.w*xv.w;
                a3 += u3.x*xv.x + u3.y*xv.y + u3.z*xv.z + u3.w*xv.w;
            }
            #pragma unroll
            for (int o = 16; o; o >>= 1) {
                a0 += __shfl_xor_sync(0xffffffffu, a0, o);
                a1 += __shfl_xor_sync(0xffffffffu, a1, o);
                a2 += __shfl_xor_sync(0xffffffffu, a2, o);
                a3 += __shfl_xor_sync(0xffffffffu, a3, o);
            }
            if (lane == 0) {
                part[(row0 + 0) * 2 + colhalf] = a0;
                part[(row0 + 1) * 2 + colhalf] = a1;
                part[(row0 + 2) * 2 + colhalf] = a2;
                part[(row0 + 3) * 2 + colhalf] = a3;
            }
        }
        __syncthreads();
        if (tid < ROWS) {
            const float fr = part[2 * tid] + part[2 * tid + 1];
            __stcg(&g_p[myrow], 1.0f - expf(kk * fr));
        }
        gen++; gridsync(gen);

        // ===== Phase B: nw = R @ p ; compartment update ; traj out =====
        {
            const float4* gp4 = (const float4*)g_p;
            xs4[tid]       = __ldcg(gp4 + tid);
            xs4[tid + 256] = __ldcg(gp4 + tid + 256);
        }
        __syncthreads();
        {
            float a0 = 0.f, a1 = 0.f, a2 = 0.f, a3 = 0.f;
            #pragma unroll 4
            for (int j = 0; j < 8; j++) {
                const float4 xv = xw[j * 32];
                const float4 u0 = Ra[j * 32];
                const float4 u1 = Rb[j * 32];
                const float4 u2 = Rc[j * 32];
                const float4 u3 = Rd[j * 32];
                a0 += u0.x*xv.x + u0.y*xv.y + u0.z*xv.z + u0.w*xv.w;
                a1 += u1.x*xv.x + u1.y*xv.y + u1.z*xv.z + u1.w*xv.w;
                a2 += u2.x*xv.x + u2.y*xv.y + u2.z*xv.z + u2.w*xv.w;
                a3 += u3.x*xv.x + u3.y*xv.y + u3.z*xv.z + u3.w*xv.w;
            }
            #pragma unroll
            for (int o = 16; o; o >>= 1) {
                a0 += __shfl_xor_sync(0xffffffffu, a0, o);
                a1 += __shfl_xor_sync(0xffffffffu, a1, o);
                a2 += __shfl_xor_sync(0xffffffffu, a2, o);
                a3 += __shfl_xor_sync(0xffffffffu, a3, o);
            }
            if (lane == 0) {
                part[(row0 + 0) * 2 + colhalf] = a0;
                part[(row0 + 1) * 2 + colhalf] = a1;
                part[(row0 + 2) * 2 + colhalf] = a2;
                part[(row0 + 3) * 2 + colhalf] = a3;
            }
        }
        __syncthreads();
        if (tid < ROWS) {
            const float acc = part[2 * tid] + part[2 * tid + 1];
            const float s   = r0 + r1 + r2 + r3;
            const float nw  = (1.0f - s) * acc;
            float n0 = r0 * Tr[0] + r1 * Tr[4] + r2 * Tr[8]  + r3 * Tr[12] + nw;
            float n1 = r0 * Tr[1] + r1 * Tr[5] + r2 * Tr[9]  + r3 * Tr[13];
            float n2 = r0 * Tr[2] + r1 * Tr[6] + r2 * Tr[10] + r3 * Tr[14];
            float n3 = r0 * Tr[3] + r1 * Tr[7] + r2 * Tr[11] + r3 * Tr[15];
            n0 = fminf(fmaxf(n0, 0.0f), 1e10f);
            n1 = fminf(fmaxf(n1, 0.0f), 1e10f);
            n2 = fminf(fmaxf(n2, 0.0f), 1e10f);
            n3 = fminf(fmaxf(n3, 0.0f), 1e10f);
            r0 = n0; r1 = n1; r2 = n2; r3 = n3;
            __stcg(&g_x[myrow], n0);                      // next step's x

            const float S = 1.0f - (n0 + n1 + n2 + n3);   // AddSusceptibleLayer
            float* o = out + ((size_t)t * MM + myrow) * (NC + 1);
            o[0] = S; o[1] = n0; o[2] = n1; o[3] = n2; o[4] = n3;
            dAcc += (double)(fabsf(S) + fabsf(n0) + fabsf(n1) + fabsf(n2) + fabsf(n3));
        }
        gen++; gridsync(gen);
    }

    // ---- agreement = mean(|traj|), fully deterministic reduction ----
    if (tid < ROWS) dsum[tid] = dAcc;
    __syncthreads();
    if (tid == 0) {
        double s = 0.0;
        for (int i = 0; i < ROWS; i++) s += dsum[i];
        g_bsum[blk] = s;
    }
    gen++; gridsync(gen);
    if (blk == 0 && tid == 0 && out_size > TRAJ_ELEMS) {
        double s = 0.0;
        for (int i = 0; i < NBLK; i++) s += __ldcg(&g_bsum[i]);
        out[TRAJ_ELEMS] = (float)(s / (double)TRAJ_ELEMS);
    }
}

extern "C" void kernel_launch(void* const* d_in, const int* in_sizes, int n_in,
                              void* d_out, int out_size)
{
    // Identify inputs by element count: R: 2048*2048, T: 4*4, rho0: 2048*4
    const float* R    = nullptr;
    const float* Tm   = nullptr;
    const float* rho0 = nullptr;
    for (int i = 0; i < n_in; i++) {
        if      (in_sizes[i] == MM * MM) R    = (const float*)d_in[i];
        else if (in_sizes[i] == NC * NC) Tm   = (const float*)d_in[i];
        else if (in_sizes[i] == MM * NC) rho0 = (const float*)d_in[i];
    }
    if (!R    && n_in > 0) R    = (const float*)d_in[0];
    if (!Tm   && n_in > 1) Tm   = (const float*)d_in[1];
    if (!rho0 && n_in > 2) rho0 = (const float*)d_in[2];

    cudaFuncSetAttribute(metasim_kernel,
                         cudaFuncAttributeMaxDynamicSharedMemorySize,
                         SMEM_BYTES);

    metasim_kernel<<<NBLK, NTHREADS, SMEM_BYTES>>>(R, Tm, rho0,
                                                   (float*)d_out, out_size);
}

// round 9
// speedup vs baseline: 2.1049x; 2.1049x over previous
#include <cuda_runtime.h>
#include <math.h>

// Problem constants
#define MM       2048           // patches
#define NC       4              // compartments
#define NSTEPS   128
#define BETA_F   0.25f
#define TRAJ_ELEMS (NSTEPS * MM * (NC + 1))   // 1310720

// 128 persistent blocks, 16 rows of R each, 256 threads.
// SMEM ~136KB => 1 block/SM => all 128 blocks co-resident (148/152 SMs),
// so the software grid barrier cannot deadlock.
#define NBLK     128
#define ROWS     16
#define NTHREADS 256
#define NGRP     16             // barrier tree: 16 groups x 8 blocks
#define PAD      32             // 32 uints = 128B padding between counters

// SMEM: R tile (16*2048 f32) + x vector (2048 f32) + 32 partials + 16 doubles
#define SMEM_BYTES ((ROWS * MM + MM + 32) * 4 + 16 * 8)

// -------- persistent device state (monotonic / re-derived every launch) -----
__device__ float        g_x[MM];             // rho[:,0] (phase-A input)
__device__ float        g_p[MM];             // infect_prob (phase-B input)
__device__ float        g_part[NBLK * MM];   // per-block column partials
__device__ double       g_bsum[NBLK];        // per-block |traj| sums
__device__ unsigned int g_grp[NGRP * PAD];   // group arrival counters (padded)
__device__ unsigned int g_root_ctr;          // root arrival counter
__device__ unsigned int g_bar_gen;           // released generation

// Grid barrier built ONLY from measured-cheap primitives (R3 recipe), with
// the single measured cost (128-way same-address RMW serialization, ~3.5K cyc)
// removed via a 2-level tree of plain relaxed atomics:
//   arrival:  __threadfence (publish) -> atomicAdd on my group counter
//             (8 contenders) -> group-last atomicAdd on root (16 contenders)
//   release:  root-last atomicExch(g_bar_gen, target)
//   wait:     1 poller/block, plain volatile load + __nanosleep throttle
// No acquire/acq_rel PTX anywhere: every acquire-flavored variant (R5/R7/R8)
// measured 1.5-3x slower per barrier than this pattern's components.
// Monotonic counters => safe across CUDA-graph replays (after generation n:
// g_grp[i]==8n, g_root_ctr==16n, g_bar_gen==n; each launch resumes from the
// current value).
__device__ __forceinline__ void gridsync(unsigned int target) {
    __syncthreads();
    if (threadIdx.x == 0) {
        __threadfence();                                  // publish prior stores
        unsigned int v = atomicAdd(&g_grp[(blockIdx.x >> 3) * PAD], 1u);
        if (v == target * 8u - 1u) {                      // last of my 8-block group
            unsigned int r = atomicAdd(&g_root_ctr, 1u);
            if (r == target * (unsigned)NGRP - 1u) {      // last block overall
                atomicExch(&g_bar_gen, target);           // release generation
            }
        }
        while ((int)(*((volatile unsigned int*)&g_bar_gen) - target) < 0)
            __nanosleep(64);
    }
    __syncthreads();
}

__global__ void __launch_bounds__(NTHREADS, 1)
metasim_kernel(const float* __restrict__ Rg,
               const float* __restrict__ Tg,
               const float* __restrict__ rho0,
               float* __restrict__ out,
               int out_size)
{
    extern __shared__ float smem[];
    float*  Rs   = smem;                   // [ROWS][MM]
    float*  xs   = Rs + ROWS * MM;         // [MM] staged vector
    float*  part = xs + MM;                // [16 rows][2 halves]
    double* dsum = (double*)(part + 32);   // [16], 8B aligned

    const int tid     = threadIdx.x;
    const int blk     = blockIdx.x;
    const int w       = tid >> 5;
    const int lane    = tid & 31;
    const int rowbase = blk * ROWS;
    const int rgrp    = w >> 1;            // 4-row group 0..3
    const int colhalf = w & 1;             // 0: cols 0..1023, 1: 1024..2047
    const int row0    = 4 * rgrp;

    // starting generation (all counters consistent at every launch boundary)
    unsigned int gen = *((volatile unsigned int*)&g_bar_gen);

    // ---- load this block's 16 rows of R into SMEM (once) ----
    {
        const float4* Rg4 = (const float4*)Rg + (size_t)rowbase * (MM / 4);
        float4* Rs4 = (float4*)Rs;
        #pragma unroll 4
        for (int k = tid; k < ROWS * MM / 4; k += NTHREADS) Rs4[k] = Rg4[k];
    }

    // ---- per-row state lives in tid<16 ----
    const int myrow = rowbase + tid;       // valid for tid < ROWS
    float r0 = 0.f, r1 = 0.f, r2 = 0.f, r3 = 0.f, kk = 0.f;
    float Tr[16];
    if (tid < ROWS) {
        #pragma unroll
        for (int i = 0; i < 16; i++) Tr[i] = Tg[i];
        r0 = rho0[myrow * 4 + 0];
        r1 = rho0[myrow * 4 + 1];
        r2 = rho0[myrow * 4 + 2];
        r3 = rho0[myrow * 4 + 3];
        __stcg(&g_x[myrow], r0);           // initial x = rho0[:,0]
    }
    __syncthreads();                       // Rs ready for column sums

    // ---- deterministic ntot: per-block column partials (no float atomics) --
    for (int c = tid; c < MM; c += NTHREADS) {
        float s = 0.f;
        #pragma unroll
        for (int r = 0; r < ROWS; r++) s += Rs[r * MM + c];
        __stcg(&g_part[blk * MM + c], s);
    }
    gen++; gridsync(gen);                  // partials + g_x visible grid-wide

    if (tid < ROWS) {                      // ntot for own rows, fixed sum order
        float s = 0.f;
        #pragma unroll 8
        for (int bb = 0; bb < NBLK; bb++) s += __ldcg(&g_part[bb * MM + myrow]);
        kk = -BETA_F / s;
    }

    // warp's 4 R-row pointers over its column half (float4 granularity)
    const float4* Ra = (const float4*)(Rs + (row0 + 0) * MM) + colhalf * 256 + lane;
    const float4* Rb = (const float4*)(Rs + (row0 + 1) * MM) + colhalf * 256 + lane;
    const float4* Rc = (const float4*)(Rs + (row0 + 2) * MM) + colhalf * 256 + lane;
    const float4* Rd = (const float4*)(Rs + (row0 + 3) * MM) + colhalf * 256 + lane;
    float4* xs4  = (float4*)xs;
    const float4* xw = xs4 + colhalf * 256 + lane;

    double dAcc = 0.0;

    for (int t = 0; t < NSTEPS; t++) {
        // ===== Phase A: frac = R @ x ; p = 1 - exp(-beta*frac/ntot) =====
        {
            const float4* gx4 = (const float4*)g_x;
            xs4[tid]       = __ldcg(gx4 + tid);
            xs4[tid + 256] = __ldcg(gx4 + tid + 256);
        }
        __syncthreads();
        {
            float a0 = 0.f, a1 = 0.f, a2 = 0.f, a3 = 0.f;
            #pragma unroll 4
            for (int j = 0; j < 8; j++) {
                const float4 xv = xw[j * 32];
                const float4 u0 = Ra[j * 32];
                const float4 u1 = Rb[j * 32];
                const float4 u2 = Rc[j * 32];
                const float4 u3 = Rd[j * 32];
                a0 += u0.x*xv.x + u0.y*xv.y + u0.z*xv.z + u0.w*xv.w;
                a1 += u1.x*xv.x + u1.y*xv.y + u1.z*xv.z + u1.w*xv.w;
                a2 += u2.x*xv.x + u2.y*xv.y + u2.z*xv.z + u2.w*xv.w;
                a3 += u3.x*xv.x + u3.y*xv.y + u3.z*xv.z + u3.w*xv.w;
            }
            #pragma unroll
            for (int o = 16; o; o >>= 1) {
                a0 += __shfl_xor_sync(0xffffffffu, a0, o);
                a1 += __shfl_xor_sync(0xffffffffu, a1, o);
                a2 += __shfl_xor_sync(0xffffffffu, a2, o);
                a3 += __shfl_xor_sync(0xffffffffu, a3, o);
            }
            if (lane == 0) {
                part[(row0 + 0) * 2 + colhalf] = a0;
                part[(row0 + 1) * 2 + colhalf] = a1;
                part[(row0 + 2) * 2 + colhalf] = a2;
                part[(row0 + 3) * 2 + colhalf] = a3;
            }
        }
        __syncthreads();
        if (tid < ROWS) {
            const float fr = part[2 * tid] + part[2 * tid + 1];
            __stcg(&g_p[myrow], 1.0f - expf(kk * fr));
        }
        gen++; gridsync(gen);

        // ===== Phase B: nw = R @ p ; compartment update ; traj out =====
        {
            const float4* gp4 = (const float4*)g_p;
            xs4[tid]       = __ldcg(gp4 + tid);
            xs4[tid + 256] = __ldcg(gp4 + tid + 256);
        }
        __syncthreads();
        {
            float a0 = 0.f, a1 = 0.f, a2 = 0.f, a3 = 0.f;
            #pragma unroll 4
            for (int j = 0; j < 8; j++) {
                const float4 xv = xw[j * 32];
                const float4 u0 = Ra[j * 32];
                const float4 u1 = Rb[j * 32];
                const float4 u2 = Rc[j * 32];
                const float4 u3 = Rd[j * 32];
                a0 += u0.x*xv.x + u0.y*xv.y + u0.z*xv.z + u0.w*xv.w;
                a1 += u1.x*xv.x + u1.y*xv.y + u1.z*xv.z + u1.w*xv.w;
                a2 += u2.x*xv.x + u2.y*xv.y + u2.z*xv.z + u2.w*xv.w;
                a3 += u3.x*xv.x + u3.y*xv.y + u3.z*xv.z + u3.w*xv.w;
            }
            #pragma unroll
            for (int o = 16; o; o >>= 1) {
                a0 += __shfl_xor_sync(0xffffffffu, a0, o);
                a1 += __shfl_xor_sync(0xffffffffu, a1, o);
                a2 += __shfl_xor_sync(0xffffffffu, a2, o);
                a3 += __shfl_xor_sync(0xffffffffu, a3, o);
            }
            if (lane == 0) {
                part[(row0 + 0) * 2 + colhalf] = a0;
                part[(row0 + 1) * 2 + colhalf] = a1;
                part[(row0 + 2) * 2 + colhalf] = a2;
                part[(row0 + 3) * 2 + colhalf] = a3;
            }
        }
        __syncthreads();
        if (tid < ROWS) {
            const float acc = part[2 * tid] + part[2 * tid + 1];
            const float s   = r0 + r1 + r2 + r3;
            const float nw  = (1.0f - s) * acc;
            float n0 = r0 * Tr[0] + r1 * Tr[4] + r2 * Tr[8]  + r3 * Tr[12] + nw;
            float n1 = r0 * Tr[1] + r1 * Tr[5] + r2 * Tr[9]  + r3 * Tr[13];
            float n2 = r0 * Tr[2] + r1 * Tr[6] + r2 * Tr[10] + r3 * Tr[14];
            float n3 = r0 * Tr[3] + r1 * Tr[7] + r2 * Tr[11] + r3 * Tr[15];
            n0 = fminf(fmaxf(n0, 0.0f), 1e10f);
            n1 = fminf(fmaxf(n1, 0.0f), 1e10f);
            n2 = fminf(fmaxf(n2, 0.0f), 1e10f);
            n3 = fminf(fmaxf(n3, 0.0f), 1e10f);
            r0 = n0; r1 = n1; r2 = n2; r3 = n3;
            __stcg(&g_x[myrow], n0);                      // next step's x

            const float S = 1.0f - (n0 + n1 + n2 + n3);   // AddSusceptibleLayer
            float* o = out + ((size_t)t * MM + myrow) * (NC + 1);
            o[0] = S; o[1] = n0; o[2] = n1; o[3] = n2; o[4] = n3;
            dAcc += (double)(fabsf(S) + fabsf(n0) + fabsf(n1) + fabsf(n2) + fabsf(n3));
        }
        gen++; gridsync(gen);
    }

    // ---- agreement = mean(|traj|), fully deterministic reduction ----
    if (tid < ROWS) dsum[tid] = dAcc;
    __syncthreads();
    if (tid == 0) {
        double s = 0.0;
        for (int i = 0; i < ROWS; i++) s += dsum[i];
        g_bsum[blk] = s;
    }
    gen++; gridsync(gen);
    if (blk == 0 && tid == 0 && out_size > TRAJ_ELEMS) {
        double s = 0.0;
        for (int i = 0; i < NBLK; i++) s += __ldcg(&g_bsum[i]);
        out[TRAJ_ELEMS] = (float)(s / (double)TRAJ_ELEMS);
    }
}

extern "C" void kernel_launch(void* const* d_in, const int* in_sizes, int n_in,
                              void* d_out, int out_size)
{
    // Identify inputs by element count: R: 2048*2048, T: 4*4, rho0: 2048*4
    const float* R    = nullptr;
    const float* Tm   = nullptr;
    const float* rho0 = nullptr;
    for (int i = 0; i < n_in; i++) {
        if      (in_sizes[i] == MM * MM) R    = (const float*)d_in[i];
        else if (in_sizes[i] == NC * NC) Tm   = (const float*)d_in[i];
        else if (in_sizes[i] == MM * NC) rho0 = (const float*)d_in[i];
    }
    if (!R    && n_in > 0) R    = (const float*)d_in[0];
    if (!Tm   && n_in > 1) Tm   = (const float*)d_in[1];
    if (!rho0 && n_in > 2) rho0 = (const float*)d_in[2];

    cudaFuncSetAttribute(metasim_kernel,
                         cudaFuncAttributeMaxDynamicSharedMemorySize,
                         SMEM_BYTES);

    metasim_kernel<<<NBLK, NTHREADS, SMEM_BYTES>>>(R, Tm, rho0,
                                                   (float*)d_out, out_size);
}